// round 1
// baseline (speedup 1.0000x reference)
#include <cuda_runtime.h>
#include <math_constants.h>

#define D_MODEL 1024
#define NHEADS 16
#define DK 64
#define BATCH 4
#define SEQ 2048
#define MROWS (BATCH * SEQ)   // 8192

// Scratch (allocation-free rule: __device__ globals), 4 x 32 MB
__device__ float g_q[(size_t)MROWS * D_MODEL];
__device__ float g_k[(size_t)MROWS * D_MODEL];
__device__ float g_v[(size_t)MROWS * D_MODEL];
__device__ float g_a[(size_t)MROWS * D_MODEL];

// ---------------------------------------------------------------------------
// SGEMM: C[M,N] = A[M,K] @ B[K,N] + bias[N]
// 128x128 block tile, BK=8, 256 threads, 8x8 register tile per thread.
// ---------------------------------------------------------------------------
__global__ __launch_bounds__(256, 2)
void sgemm_bias(const float* __restrict__ A, const float* __restrict__ B,
                const float* __restrict__ bias, float* __restrict__ C,
                int M, int N, int K)
{
    __shared__ float As[8][132];   // transposed A tile, padded (conflict-free stores)
    __shared__ float Bs[8][128];

    const int tid = threadIdx.x;
    const int bx = blockIdx.x, by = blockIdx.y;

    // A tile load: 128 rows x 8 cols, one float4 per thread
    const int a_row = tid >> 1;
    const int a_col = (tid & 1) << 2;
    // B tile load: 8 rows x 128 cols, one float4 per thread
    const int b_row = tid >> 5;
    const int b_col = (tid & 31) << 2;

    const float* Ap = A + (size_t)(by * 128 + a_row) * K + a_col;
    const float* Bp = B + (size_t)b_row * N + bx * 128 + b_col;

    const int tr = (tid >> 4) << 3;   // 8 rows
    const int tc = (tid & 15) << 3;   // 8 cols

    float acc[8][8];
#pragma unroll
    for (int i = 0; i < 8; i++)
#pragma unroll
        for (int j = 0; j < 8; j++) acc[i][j] = 0.0f;

    for (int k0 = 0; k0 < K; k0 += 8) {
        float4 av = *(const float4*)Ap;
        float4 bv = *(const float4*)Bp;
        As[a_col + 0][a_row] = av.x;
        As[a_col + 1][a_row] = av.y;
        As[a_col + 2][a_row] = av.z;
        As[a_col + 3][a_row] = av.w;
        *(float4*)&Bs[b_row][b_col] = bv;
        __syncthreads();

#pragma unroll
        for (int kk = 0; kk < 8; kk++) {
            float ar[8], br[8];
            *(float4*)(ar)     = *(const float4*)&As[kk][tr];
            *(float4*)(ar + 4) = *(const float4*)&As[kk][tr + 4];
            *(float4*)(br)     = *(const float4*)&Bs[kk][tc];
            *(float4*)(br + 4) = *(const float4*)&Bs[kk][tc + 4];
#pragma unroll
            for (int i = 0; i < 8; i++)
#pragma unroll
                for (int j = 0; j < 8; j++)
                    acc[i][j] = fmaf(ar[i], br[j], acc[i][j]);
        }
        __syncthreads();
        Ap += 8;
        Bp += (size_t)8 * N;
    }

    float bb[8];
    *(float4*)(bb)     = *(const float4*)&bias[bx * 128 + tc];
    *(float4*)(bb + 4) = *(const float4*)&bias[bx * 128 + tc + 4];

#pragma unroll
    for (int i = 0; i < 8; i++) {
        float* Cp = C + (size_t)(by * 128 + tr + i) * N + bx * 128 + tc;
        float4 o0 = make_float4(acc[i][0] + bb[0], acc[i][1] + bb[1],
                                acc[i][2] + bb[2], acc[i][3] + bb[3]);
        float4 o1 = make_float4(acc[i][4] + bb[4], acc[i][5] + bb[5],
                                acc[i][6] + bb[6], acc[i][7] + bb[7]);
        *(float4*)(Cp)     = o0;
        *(float4*)(Cp + 4) = o1;
    }
}

// ---------------------------------------------------------------------------
// Causal flash attention, fp32. One block = (batch b, head h, 64-row q tile).
// 256 threads; per thread a 4x4 tile of the 64x64 score block.
//   rows: r0 = (tid/16)*4 + ri           (16 row-groups of 16 threads)
//   cols: c  = (tid%16) + 16*ci          (interleaved -> conflict-free LDS)
// Q,K stored transposed [d][row] in smem -> stride-64 reads are conflict-free.
// Online softmax with 16-lane shfl reductions; P broadcast to PV via shfl.
// ---------------------------------------------------------------------------
__global__ __launch_bounds__(256, 2)
void flash_attn(const float* __restrict__ Q, const float* __restrict__ K,
                const float* __restrict__ V, float* __restrict__ O)
{
    __shared__ float Qs[64][64];   // [d][r], pre-scaled by 1/sqrt(dk)
    __shared__ float Ks[64][64];   // [d][c]
    __shared__ float Vs[64][64];   // [j][d]

    const int tid = threadIdx.x;
    const int qt = blockIdx.x;
    const int h  = blockIdx.y;
    const int b  = blockIdx.z;
    const int q0 = qt * 64;

    const size_t base = ((size_t)b * SEQ) * D_MODEL + (size_t)h * DK;

    const int r0 = (tid >> 4) << 2;   // base of 4 rows
    const int c0 = tid & 15;          // col offset; cols = c0 + 16*ci

    // loader mapping: each thread loads row lr, 16 contiguous cols at lc
    const int lr = tid >> 2;
    const int lc = (tid & 3) << 4;

    {
        const float* qp = Q + base + (size_t)(q0 + lr) * D_MODEL + lc;
#pragma unroll
        for (int i = 0; i < 16; i += 4) {
            float4 t4 = *(const float4*)(qp + i);
            Qs[lc + i + 0][lr] = t4.x * 0.125f;
            Qs[lc + i + 1][lr] = t4.y * 0.125f;
            Qs[lc + i + 2][lr] = t4.z * 0.125f;
            Qs[lc + i + 3][lr] = t4.w * 0.125f;
        }
    }

    float m[4], l[4], o[4][4];
#pragma unroll
    for (int ri = 0; ri < 4; ri++) {
        m[ri] = -CUDART_INF_F;
        l[ri] = 0.0f;
#pragma unroll
        for (int ci = 0; ci < 4; ci++) o[ri][ci] = 0.0f;
    }

    const unsigned halfsel = (unsigned)(tid & 16);

    for (int kt = 0; kt <= qt; kt++) {
        const int k0 = kt * 64;

        __syncthreads();   // prior readers of Ks/Vs done (also covers Qs on iter 0)
        {
            const float* kp = K + base + (size_t)(k0 + lr) * D_MODEL + lc;
            const float* vp = V + base + (size_t)(k0 + lr) * D_MODEL + lc;
#pragma unroll
            for (int i = 0; i < 16; i += 4) {
                float4 t4 = *(const float4*)(kp + i);
                Ks[lc + i + 0][lr] = t4.x;
                Ks[lc + i + 1][lr] = t4.y;
                Ks[lc + i + 2][lr] = t4.z;
                Ks[lc + i + 3][lr] = t4.w;
                *(float4*)&Vs[lr][lc + i] = *(const float4*)(vp + i);
            }
        }
        __syncthreads();

        // --- scores: s[ri][ci] = q_row . k_col (Q pre-scaled) ---
        float s[4][4];
#pragma unroll
        for (int ri = 0; ri < 4; ri++)
#pragma unroll
            for (int ci = 0; ci < 4; ci++) s[ri][ci] = 0.0f;

#pragma unroll 8
        for (int d = 0; d < 64; d++) {
            float qv[4], kv[4];
#pragma unroll
            for (int ri = 0; ri < 4; ri++) qv[ri] = Qs[d][r0 + ri];
#pragma unroll
            for (int ci = 0; ci < 4; ci++) kv[ci] = Ks[d][c0 + 16 * ci];
#pragma unroll
            for (int ri = 0; ri < 4; ri++)
#pragma unroll
                for (int ci = 0; ci < 4; ci++)
                    s[ri][ci] = fmaf(qv[ri], kv[ci], s[ri][ci]);
        }

        // causal mask only needed on the diagonal tile
        if (kt == qt) {
#pragma unroll
            for (int ri = 0; ri < 4; ri++)
#pragma unroll
                for (int ci = 0; ci < 4; ci++)
                    if (c0 + 16 * ci > r0 + ri) s[ri][ci] = -CUDART_INF_F;
        }

        // --- online softmax (row state replicated across the 16 lanes/row) ---
#pragma unroll
        for (int ri = 0; ri < 4; ri++) {
            float mt = fmaxf(fmaxf(s[ri][0], s[ri][1]), fmaxf(s[ri][2], s[ri][3]));
#pragma unroll
            for (int w = 1; w < 16; w <<= 1)
                mt = fmaxf(mt, __shfl_xor_sync(0xffffffffu, mt, w));
            const float mn = fmaxf(m[ri], mt);
            const float alpha = __expf(m[ri] - mn);
            m[ri] = mn;
            float rs = 0.0f;
#pragma unroll
            for (int ci = 0; ci < 4; ci++) {
                s[ri][ci] = __expf(s[ri][ci] - mn);
                rs += s[ri][ci];
            }
#pragma unroll
            for (int w = 1; w < 16; w <<= 1)
                rs += __shfl_xor_sync(0xffffffffu, rs, w);
            l[ri] = l[ri] * alpha + rs;
#pragma unroll
            for (int ci = 0; ci < 4; ci++) o[ri][ci] *= alpha;
        }

        // --- PV: o[ri][ci] += sum_j p[r][j] * V[j][d], p broadcast via shfl ---
#pragma unroll
        for (int cs = 0; cs < 4; cs++) {
#pragma unroll
            for (int jj = 0; jj < 16; jj++) {
                const int j = cs * 16 + jj;
                const unsigned src = halfsel | (unsigned)jj;
                const float p0 = __shfl_sync(0xffffffffu, s[0][cs], src);
                const float p1 = __shfl_sync(0xffffffffu, s[1][cs], src);
                const float p2 = __shfl_sync(0xffffffffu, s[2][cs], src);
                const float p3 = __shfl_sync(0xffffffffu, s[3][cs], src);
                const float v0 = Vs[j][c0];
                const float v1 = Vs[j][c0 + 16];
                const float v2 = Vs[j][c0 + 32];
                const float v3 = Vs[j][c0 + 48];
                o[0][0] = fmaf(p0, v0, o[0][0]);
                o[0][1] = fmaf(p0, v1, o[0][1]);
                o[0][2] = fmaf(p0, v2, o[0][2]);
                o[0][3] = fmaf(p0, v3, o[0][3]);
                o[1][0] = fmaf(p1, v0, o[1][0]);
                o[1][1] = fmaf(p1, v1, o[1][1]);
                o[1][2] = fmaf(p1, v2, o[1][2]);
                o[1][3] = fmaf(p1, v3, o[1][3]);
                o[2][0] = fmaf(p2, v0, o[2][0]);
                o[2][1] = fmaf(p2, v1, o[2][1]);
                o[2][2] = fmaf(p2, v2, o[2][2]);
                o[2][3] = fmaf(p2, v3, o[2][3]);
                o[3][0] = fmaf(p3, v0, o[3][0]);
                o[3][1] = fmaf(p3, v1, o[3][1]);
                o[3][2] = fmaf(p3, v2, o[3][2]);
                o[3][3] = fmaf(p3, v3, o[3][3]);
            }
        }
    }

    // epilogue: normalize and write
#pragma unroll
    for (int ri = 0; ri < 4; ri++) {
        const float inv = 1.0f / l[ri];
        float* op = O + base + (size_t)(q0 + r0 + ri) * D_MODEL;
        op[c0]      = o[ri][0] * inv;
        op[c0 + 16] = o[ri][1] * inv;
        op[c0 + 32] = o[ri][2] * inv;
        op[c0 + 48] = o[ri][3] * inv;
    }
}

// ---------------------------------------------------------------------------
extern "C" void kernel_launch(void* const* d_in, const int* in_sizes, int n_in,
                              void* d_out, int out_size)
{
    (void)in_sizes; (void)n_in; (void)out_size;
    const float* x  = (const float*)d_in[0];
    const float* Wq = (const float*)d_in[1];
    const float* bq = (const float*)d_in[2];
    const float* Wk = (const float*)d_in[3];
    const float* bk = (const float*)d_in[4];
    const float* Wv = (const float*)d_in[5];
    const float* bv = (const float*)d_in[6];
    const float* Wo = (const float*)d_in[7];
    const float* bo = (const float*)d_in[8];
    float* out = (float*)d_out;

    float *qb = nullptr, *kb = nullptr, *vb = nullptr, *ab = nullptr;
    cudaGetSymbolAddress((void**)&qb, g_q);
    cudaGetSymbolAddress((void**)&kb, g_k);
    cudaGetSymbolAddress((void**)&vb, g_v);
    cudaGetSymbolAddress((void**)&ab, g_a);

    dim3 gg(D_MODEL / 128, MROWS / 128);   // (8, 64)
    sgemm_bias<<<gg, 256>>>(x, Wq, bq, qb, MROWS, D_MODEL, D_MODEL);
    sgemm_bias<<<gg, 256>>>(x, Wk, bk, kb, MROWS, D_MODEL, D_MODEL);
    sgemm_bias<<<gg, 256>>>(x, Wv, bv, vb, MROWS, D_MODEL, D_MODEL);

    dim3 ga(SEQ / 64, NHEADS, BATCH);      // (32, 16, 4)
    flash_attn<<<ga, 256>>>(qb, kb, vb, ab);

    sgemm_bias<<<gg, 256>>>(ab, Wo, bo, out, MROWS, D_MODEL, D_MODEL);
}

// round 3
// speedup vs baseline: 1.4361x; 1.4361x over previous
#include <cuda_runtime.h>
#include <cuda_bf16.h>
#include <math_constants.h>
#include <cstdint>

#define D_MODEL 1024
#define NHEADS 16
#define DK 64
#define BATCH 4
#define SEQ 2048
#define MROWS (BATCH * SEQ)   // 8192

// ---------------------------------------------------------------------------
// Scratch (allocation-free rule: __device__ globals)
// ---------------------------------------------------------------------------
__device__ float g_q[(size_t)MROWS * D_MODEL];
__device__ float g_k[(size_t)MROWS * D_MODEL];
__device__ float g_v[(size_t)MROWS * D_MODEL];
__device__ float g_a[(size_t)MROWS * D_MODEL];
__device__ __nv_bfloat16 g_xh[(size_t)MROWS * D_MODEL];
__device__ __nv_bfloat16 g_xl[(size_t)MROWS * D_MODEL];
// transposed weights [N][K], hi/lo, 4 matrices
__device__ __nv_bfloat16 g_wth[4][(size_t)D_MODEL * D_MODEL];
__device__ __nv_bfloat16 g_wtl[4][(size_t)D_MODEL * D_MODEL];

// ---------------------------------------------------------------------------
// helpers (base-target PTX only: cp.async / ldmatrix / mma.sync)
// ---------------------------------------------------------------------------
__device__ __forceinline__ uint32_t smem_u32(const void* p) {
    uint32_t a;
    asm("{ .reg .u64 t; cvta.to.shared.u64 t, %1; cvt.u32.u64 %0, t; }"
        : "=r"(a) : "l"(p));
    return a;
}
#define SMEM_SWIZZLE_128B(off) ((off) ^ (((off) >> 3) & 0x70))

#define CP_ASYNC16(dst, src) \
    asm volatile("cp.async.cg.shared.global [%0], [%1], 16;" \
                 :: "r"((uint32_t)(dst)), "l"(src) : "memory")
#define CP_COMMIT() asm volatile("cp.async.commit_group;" ::: "memory")
#define CP_WAIT0()  asm volatile("cp.async.wait_group 0;" ::: "memory")

__device__ __forceinline__ void ldsm_x4(uint32_t& r0, uint32_t& r1,
                                        uint32_t& r2, uint32_t& r3, uint32_t addr) {
    asm volatile("ldmatrix.sync.aligned.m8n8.x4.shared.b16 {%0,%1,%2,%3}, [%4];"
                 : "=r"(r0), "=r"(r1), "=r"(r2), "=r"(r3) : "r"(addr));
}
__device__ __forceinline__ void ldsm_x2(uint32_t& r0, uint32_t& r1, uint32_t addr) {
    asm volatile("ldmatrix.sync.aligned.m8n8.x2.shared.b16 {%0,%1}, [%2];"
                 : "=r"(r0), "=r"(r1) : "r"(addr));
}
__device__ __forceinline__ void mma_16816(float* c, const uint32_t* a, const uint32_t* b) {
    asm volatile(
        "mma.sync.aligned.m16n8k16.row.col.f32.bf16.bf16.f32 "
        "{%0,%1,%2,%3}, {%4,%5,%6,%7}, {%8,%9}, {%0,%1,%2,%3};"
        : "+f"(c[0]), "+f"(c[1]), "+f"(c[2]), "+f"(c[3])
        : "r"(a[0]), "r"(a[1]), "r"(a[2]), "r"(a[3]), "r"(b[0]), "r"(b[1]));
}

// ---------------------------------------------------------------------------
// fp32 -> bf16 hi/lo split (elementwise, float4-vectorized)
// ---------------------------------------------------------------------------
__global__ void split_f32(const float* __restrict__ in,
                          __nv_bfloat16* __restrict__ h,
                          __nv_bfloat16* __restrict__ l, int n4)
{
    int i = blockIdx.x * blockDim.x + threadIdx.x;
    if (i >= n4) return;
    float4 v = ((const float4*)in)[i];
    __nv_bfloat16 h0 = __float2bfloat16(v.x);
    __nv_bfloat16 h1 = __float2bfloat16(v.y);
    __nv_bfloat16 h2 = __float2bfloat16(v.z);
    __nv_bfloat16 h3 = __float2bfloat16(v.w);
    __nv_bfloat16 l0 = __float2bfloat16(v.x - __bfloat162float(h0));
    __nv_bfloat16 l1 = __float2bfloat16(v.y - __bfloat162float(h1));
    __nv_bfloat16 l2 = __float2bfloat16(v.z - __bfloat162float(h2));
    __nv_bfloat16 l3 = __float2bfloat16(v.w - __bfloat162float(h3));
    ((__nv_bfloat162*)h)[2 * i]     = __halves2bfloat162(h0, h1);
    ((__nv_bfloat162*)h)[2 * i + 1] = __halves2bfloat162(h2, h3);
    ((__nv_bfloat162*)l)[2 * i]     = __halves2bfloat162(l0, l1);
    ((__nv_bfloat162*)l)[2 * i + 1] = __halves2bfloat162(l2, l3);
}

// W[K][N] fp32 -> W^T[N][K] bf16 hi/lo (transpose so MMA B operand is K-major)
__global__ void split_f32_T(const float* __restrict__ W,
                            __nv_bfloat16* __restrict__ hT,
                            __nv_bfloat16* __restrict__ lT)
{
    int idx = blockIdx.x * blockDim.x + threadIdx.x;   // 1M threads
    int k = idx >> 10, n = idx & 1023;
    float v = W[idx];
    __nv_bfloat16 h = __float2bfloat16(v);
    __nv_bfloat16 l = __float2bfloat16(v - __bfloat162float(h));
    hT[(size_t)n * 1024 + k] = h;
    lT[(size_t)n * 1024 + k] = l;
}

// ---------------------------------------------------------------------------
// Tensor-core GEMM (mma.sync bf16, fp32-split 3-pass):
//   C[M,N] = A[M,K] @ BT[N,K]^T + bias
// 128x128 CTA tile, BK=64, 256 threads. Warp grid 2(m) x 4(n), warp tile 64x32.
// A, BT both K-major in smem, 128B rows with Swizzle<3,4,3>.
// ---------------------------------------------------------------------------
__global__ __launch_bounds__(256)
void gemm_bf16_mma(const __nv_bfloat16* __restrict__ Ah,
                   const __nv_bfloat16* __restrict__ Al,
                   const __nv_bfloat16* __restrict__ BTh,
                   const __nv_bfloat16* __restrict__ BTl,
                   const float* __restrict__ bias,
                   float* __restrict__ C)
{
    extern __shared__ char smem_raw[];
    const uint32_t sb0  = (smem_u32(smem_raw) + 1023u) & ~1023u;
    const uint32_t SA_H = sb0;
    const uint32_t SA_L = sb0 + 16384;
    const uint32_t SB_H = sb0 + 32768;
    const uint32_t SB_L = sb0 + 49152;

    const int tid = threadIdx.x, wid = tid >> 5, lid = tid & 31;
    const int bx = blockIdx.x, by = blockIdx.y;
    const int wm = wid >> 2;          // 0..1
    const int wn = wid & 3;           // 0..3

    const __nv_bfloat16* aH = Ah  + (size_t)(by * 128) * 1024;
    const __nv_bfloat16* aL = Al  + (size_t)(by * 128) * 1024;
    const __nv_bfloat16* bH = BTh + (size_t)(bx * 128) * 1024;
    const __nv_bfloat16* bL = BTl + (size_t)(bx * 128) * 1024;

    float acc[4][4][4];
#pragma unroll
    for (int i = 0; i < 4; i++)
#pragma unroll
        for (int j = 0; j < 4; j++)
#pragma unroll
            for (int t = 0; t < 4; t++) acc[i][j][t] = 0.0f;

    // ldmatrix source offsets (within a tile), precomputed swizzled per ks
    // A x4: row = warp_m_base + mf*16 + (lid&15); byte col = ks*32 + ((lid>>4)<<4)
    // B x2: row = warp_n_base + nf*8  + (lid&7);  byte col = ks*32 + (((lid>>3)&1)<<4)
    const int a_row_l = (lid & 15);
    const int a_cb_l  = (lid >> 4) << 4;
    const int b_row_l = (lid & 7);
    const int b_cb_l  = ((lid >> 3) & 1) << 4;

    for (int kc = 0; kc < 16; kc++) {
        __syncthreads();   // protect smem against readers of previous chunk
        // load 4 tiles of 128 rows x 64 bf16 (16B granules, SW128 swizzle)
#pragma unroll
        for (int i = 0; i < 4; i++) {
            int g = tid + i * 256;             // 0..1023
            int row = g >> 3, c16 = g & 7;
            uint32_t soff = SMEM_SWIZZLE_128B((uint32_t)(row * 128 + c16 * 16));
            size_t goff = (size_t)row * 1024 + (size_t)kc * 64 + c16 * 8;
            CP_ASYNC16(SA_H + soff, aH + goff);
            CP_ASYNC16(SA_L + soff, aL + goff);
            CP_ASYNC16(SB_H + soff, bH + goff);
            CP_ASYNC16(SB_L + soff, bL + goff);
        }
        CP_COMMIT();
        CP_WAIT0();
        __syncthreads();

        // 3 passes: Ah*Bh, Al*Bh, Ah*Bl
#pragma unroll
        for (int pass = 0; pass < 3; pass++) {
            const uint32_t sa = (pass == 1) ? SA_L : SA_H;
            const uint32_t sb = (pass == 2) ? SB_L : SB_H;
#pragma unroll
            for (int ks = 0; ks < 4; ks++) {
                uint32_t afr[4][4];
#pragma unroll
                for (int mf = 0; mf < 4; mf++) {
                    uint32_t off = (uint32_t)((wm * 64 + mf * 16 + a_row_l) * 128
                                              + ks * 32 + a_cb_l);
                    ldsm_x4(afr[mf][0], afr[mf][1], afr[mf][2], afr[mf][3],
                            sa + SMEM_SWIZZLE_128B(off));
                }
                uint32_t bfr[4][2];
#pragma unroll
                for (int nf = 0; nf < 4; nf++) {
                    uint32_t off = (uint32_t)((wn * 32 + nf * 8 + b_row_l) * 128
                                              + ks * 32 + b_cb_l);
                    ldsm_x2(bfr[nf][0], bfr[nf][1], sb + SMEM_SWIZZLE_128B(off));
                }
#pragma unroll
                for (int mf = 0; mf < 4; mf++)
#pragma unroll
                    for (int nf = 0; nf < 4; nf++)
                        mma_16816(acc[mf][nf], afr[mf], bfr[nf]);
            }
        }
    }

    // epilogue: fragment layout m16n8 -> rows (lid>>2, +8), cols (lid&3)*2, +1
    const int er = lid >> 2;
    const int ec = (lid & 3) << 1;
#pragma unroll
    for (int mf = 0; mf < 4; mf++) {
#pragma unroll
        for (int nf = 0; nf < 4; nf++) {
            const int m = by * 128 + wm * 64 + mf * 16 + er;
            const int n = bx * 128 + wn * 32 + nf * 8 + ec;
            float2 bv = *(const float2*)&bias[n];
            float2 o0 = make_float2(acc[mf][nf][0] + bv.x, acc[mf][nf][1] + bv.y);
            float2 o1 = make_float2(acc[mf][nf][2] + bv.x, acc[mf][nf][3] + bv.y);
            *(float2*)&C[(size_t)m * 1024 + n]       = o0;
            *(float2*)&C[(size_t)(m + 8) * 1024 + n] = o1;
        }
    }
}

// ---------------------------------------------------------------------------
// Causal flash attention, fp32 (unchanged).
// ---------------------------------------------------------------------------
__global__ __launch_bounds__(256, 2)
void flash_attn(const float* __restrict__ Q, const float* __restrict__ K,
                const float* __restrict__ V, float* __restrict__ O)
{
    __shared__ float Qs[64][64];   // [d][r], pre-scaled
    __shared__ float Ks[64][64];   // [d][c]
    __shared__ float Vs[64][64];   // [j][d]

    const int tid = threadIdx.x;
    const int qt = blockIdx.x;
    const int h  = blockIdx.y;
    const int b  = blockIdx.z;
    const int q0 = qt * 64;

    const size_t base = ((size_t)b * SEQ) * D_MODEL + (size_t)h * DK;

    const int r0 = (tid >> 4) << 2;
    const int c0 = tid & 15;

    const int lr = tid >> 2;
    const int lc = (tid & 3) << 4;

    {
        const float* qp = Q + base + (size_t)(q0 + lr) * D_MODEL + lc;
#pragma unroll
        for (int i = 0; i < 16; i += 4) {
            float4 t4 = *(const float4*)(qp + i);
            Qs[lc + i + 0][lr] = t4.x * 0.125f;
            Qs[lc + i + 1][lr] = t4.y * 0.125f;
            Qs[lc + i + 2][lr] = t4.z * 0.125f;
            Qs[lc + i + 3][lr] = t4.w * 0.125f;
        }
    }

    float m[4], l[4], o[4][4];
#pragma unroll
    for (int ri = 0; ri < 4; ri++) {
        m[ri] = -CUDART_INF_F;
        l[ri] = 0.0f;
#pragma unroll
        for (int ci = 0; ci < 4; ci++) o[ri][ci] = 0.0f;
    }

    const unsigned halfsel = (unsigned)(tid & 16);

    for (int kt = 0; kt <= qt; kt++) {
        const int k0 = kt * 64;

        __syncthreads();
        {
            const float* kp = K + base + (size_t)(k0 + lr) * D_MODEL + lc;
            const float* vp = V + base + (size_t)(k0 + lr) * D_MODEL + lc;
#pragma unroll
            for (int i = 0; i < 16; i += 4) {
                float4 t4 = *(const float4*)(kp + i);
                Ks[lc + i + 0][lr] = t4.x;
                Ks[lc + i + 1][lr] = t4.y;
                Ks[lc + i + 2][lr] = t4.z;
                Ks[lc + i + 3][lr] = t4.w;
                *(float4*)&Vs[lr][lc + i] = *(const float4*)(vp + i);
            }
        }
        __syncthreads();

        float s[4][4];
#pragma unroll
        for (int ri = 0; ri < 4; ri++)
#pragma unroll
            for (int ci = 0; ci < 4; ci++) s[ri][ci] = 0.0f;

#pragma unroll 8
        for (int d = 0; d < 64; d++) {
            float qv[4], kv[4];
            *(float4*)qv = *(const float4*)&Qs[d][r0];
#pragma unroll
            for (int ci = 0; ci < 4; ci++) kv[ci] = Ks[d][c0 + 16 * ci];
#pragma unroll
            for (int ri = 0; ri < 4; ri++)
#pragma unroll
                for (int ci = 0; ci < 4; ci++)
                    s[ri][ci] = fmaf(qv[ri], kv[ci], s[ri][ci]);
        }

        if (kt == qt) {
#pragma unroll
            for (int ri = 0; ri < 4; ri++)
#pragma unroll
                for (int ci = 0; ci < 4; ci++)
                    if (c0 + 16 * ci > r0 + ri) s[ri][ci] = -CUDART_INF_F;
        }

#pragma unroll
        for (int ri = 0; ri < 4; ri++) {
            float mt = fmaxf(fmaxf(s[ri][0], s[ri][1]), fmaxf(s[ri][2], s[ri][3]));
#pragma unroll
            for (int w = 1; w < 16; w <<= 1)
                mt = fmaxf(mt, __shfl_xor_sync(0xffffffffu, mt, w));
            const float mn = fmaxf(m[ri], mt);
            const float alpha = __expf(m[ri] - mn);
            m[ri] = mn;
            float rs = 0.0f;
#pragma unroll
            for (int ci = 0; ci < 4; ci++) {
                s[ri][ci] = __expf(s[ri][ci] - mn);
                rs += s[ri][ci];
            }
#pragma unroll
            for (int w = 1; w < 16; w <<= 1)
                rs += __shfl_xor_sync(0xffffffffu, rs, w);
            l[ri] = l[ri] * alpha + rs;
#pragma unroll
            for (int ci = 0; ci < 4; ci++) o[ri][ci] *= alpha;
        }

#pragma unroll
        for (int cs = 0; cs < 4; cs++) {
#pragma unroll
            for (int jj = 0; jj < 16; jj++) {
                const int j = cs * 16 + jj;
                const unsigned src = halfsel | (unsigned)jj;
                const float p0 = __shfl_sync(0xffffffffu, s[0][cs], src);
                const float p1 = __shfl_sync(0xffffffffu, s[1][cs], src);
                const float p2 = __shfl_sync(0xffffffffu, s[2][cs], src);
                const float p3 = __shfl_sync(0xffffffffu, s[3][cs], src);
                const float v0 = Vs[j][c0];
                const float v1 = Vs[j][c0 + 16];
                const float v2 = Vs[j][c0 + 32];
                const float v3 = Vs[j][c0 + 48];
                o[0][0] = fmaf(p0, v0, o[0][0]);
                o[0][1] = fmaf(p0, v1, o[0][1]);
                o[0][2] = fmaf(p0, v2, o[0][2]);
                o[0][3] = fmaf(p0, v3, o[0][3]);
                o[1][0] = fmaf(p1, v0, o[1][0]);
                o[1][1] = fmaf(p1, v1, o[1][1]);
                o[1][2] = fmaf(p1, v2, o[1][2]);
                o[1][3] = fmaf(p1, v3, o[1][3]);
                o[2][0] = fmaf(p2, v0, o[2][0]);
                o[2][1] = fmaf(p2, v1, o[2][1]);
                o[2][2] = fmaf(p2, v2, o[2][2]);
                o[2][3] = fmaf(p2, v3, o[2][3]);
                o[3][0] = fmaf(p3, v0, o[3][0]);
                o[3][1] = fmaf(p3, v1, o[3][1]);
                o[3][2] = fmaf(p3, v2, o[3][2]);
                o[3][3] = fmaf(p3, v3, o[3][3]);
            }
        }
    }

#pragma unroll
    for (int ri = 0; ri < 4; ri++) {
        const float inv = 1.0f / l[ri];
        float* op = O + base + (size_t)(q0 + r0 + ri) * D_MODEL;
        op[c0]      = o[ri][0] * inv;
        op[c0 + 16] = o[ri][1] * inv;
        op[c0 + 32] = o[ri][2] * inv;
        op[c0 + 48] = o[ri][3] * inv;
    }
}

// ---------------------------------------------------------------------------
extern "C" void kernel_launch(void* const* d_in, const int* in_sizes, int n_in,
                              void* d_out, int out_size)
{
    (void)in_sizes; (void)n_in; (void)out_size;
    const float* x  = (const float*)d_in[0];
    const float* Wq = (const float*)d_in[1];
    const float* bq = (const float*)d_in[2];
    const float* Wk = (const float*)d_in[3];
    const float* bk = (const float*)d_in[4];
    const float* Wv = (const float*)d_in[5];
    const float* bv = (const float*)d_in[6];
    const float* Wo = (const float*)d_in[7];
    const float* bo = (const float*)d_in[8];
    float* out = (float*)d_out;

    float *qb, *kb, *vb, *ab;
    __nv_bfloat16 *xh, *xl, *wth, *wtl;
    cudaGetSymbolAddress((void**)&qb, g_q);
    cudaGetSymbolAddress((void**)&kb, g_k);
    cudaGetSymbolAddress((void**)&vb, g_v);
    cudaGetSymbolAddress((void**)&ab, g_a);
    cudaGetSymbolAddress((void**)&xh, g_xh);
    cudaGetSymbolAddress((void**)&xl, g_xl);
    cudaGetSymbolAddress((void**)&wth, g_wth);
    cudaGetSymbolAddress((void**)&wtl, g_wtl);

    const size_t WSZ = (size_t)D_MODEL * D_MODEL;
    const int GEMM_SMEM = 66560;   // 64KB + alignment slack
    cudaFuncSetAttribute(gemm_bf16_mma,
                         cudaFuncAttributeMaxDynamicSharedMemorySize, GEMM_SMEM);

    // split x -> bf16 hi/lo
    split_f32<<<(MROWS * D_MODEL / 4 + 255) / 256, 256>>>(x, xh, xl, MROWS * D_MODEL / 4);
    // split + transpose weights
    split_f32_T<<<(int)(WSZ / 256), 256>>>(Wq, wth + 0 * WSZ, wtl + 0 * WSZ);
    split_f32_T<<<(int)(WSZ / 256), 256>>>(Wk, wth + 1 * WSZ, wtl + 1 * WSZ);
    split_f32_T<<<(int)(WSZ / 256), 256>>>(Wv, wth + 2 * WSZ, wtl + 2 * WSZ);
    split_f32_T<<<(int)(WSZ / 256), 256>>>(Wo, wth + 3 * WSZ, wtl + 3 * WSZ);

    dim3 gg(D_MODEL / 128, MROWS / 128);   // (8, 64)
    gemm_bf16_mma<<<gg, 256, GEMM_SMEM>>>(xh, xl, wth + 0 * WSZ, wtl + 0 * WSZ, bq, qb);
    gemm_bf16_mma<<<gg, 256, GEMM_SMEM>>>(xh, xl, wth + 1 * WSZ, wtl + 1 * WSZ, bk, kb);
    gemm_bf16_mma<<<gg, 256, GEMM_SMEM>>>(xh, xl, wth + 2 * WSZ, wtl + 2 * WSZ, bv, vb);

    dim3 ga(SEQ / 64, NHEADS, BATCH);      // (32, 16, 4)
    flash_attn<<<ga, 256>>>(qb, kb, vb, ab);

    // split attention output, reuse xh/xl
    split_f32<<<(MROWS * D_MODEL / 4 + 255) / 256, 256>>>(ab, xh, xl, MROWS * D_MODEL / 4);
    gemm_bf16_mma<<<gg, 256, GEMM_SMEM>>>(xh, xl, wth + 3 * WSZ, wtl + 3 * WSZ, bo, out);
}

// round 5
// speedup vs baseline: 3.6697x; 2.5554x over previous
#include <cuda_runtime.h>
#include <cuda_bf16.h>
#include <cuda_fp16.h>
#include <math_constants.h>
#include <cstdint>

#define D_MODEL 1024
#define NHEADS 16
#define DK 64
#define BATCH 4
#define SEQ 2048
#define MROWS (BATCH * SEQ)   // 8192

// fold 1/sqrt(dk) * log2(e) into Q so softmax runs in base-2 domain
#define QSCALE 0.18033688011112042f

// ---------------------------------------------------------------------------
// Scratch (allocation-free rule: __device__ globals)
// ---------------------------------------------------------------------------
__device__ __nv_bfloat16 g_xh[(size_t)MROWS * D_MODEL];
__device__ __nv_bfloat16 g_xl[(size_t)MROWS * D_MODEL];
__device__ __nv_bfloat16 g_qh[(size_t)MROWS * D_MODEL];
__device__ __nv_bfloat16 g_ql[(size_t)MROWS * D_MODEL];
__device__ __nv_bfloat16 g_kh[(size_t)MROWS * D_MODEL];
__device__ __nv_bfloat16 g_kl[(size_t)MROWS * D_MODEL];
__device__ __half        g_v16[(size_t)MROWS * D_MODEL];
__device__ __nv_bfloat16 g_wth[4][(size_t)D_MODEL * D_MODEL];
__device__ __nv_bfloat16 g_wtl[4][(size_t)D_MODEL * D_MODEL];

// ---------------------------------------------------------------------------
// helpers (base-target PTX only: cp.async / ldmatrix / mma.sync)
// ---------------------------------------------------------------------------
__device__ __forceinline__ uint32_t smem_u32(const void* p) {
    uint32_t a;
    asm("{ .reg .u64 t; cvta.to.shared.u64 t, %1; cvt.u32.u64 %0, t; }"
        : "=r"(a) : "l"(p));
    return a;
}
#define SMEM_SWIZZLE_128B(off) ((off) ^ (((off) >> 3) & 0x70))

#define CP_ASYNC16(dst, src) \
    asm volatile("cp.async.cg.shared.global [%0], [%1], 16;" \
                 :: "r"((uint32_t)(dst)), "l"(src) : "memory")
#define CP_COMMIT() asm volatile("cp.async.commit_group;" ::: "memory")
#define CP_WAIT0()  asm volatile("cp.async.wait_group 0;" ::: "memory")

__device__ __forceinline__ void ldsm_x4(uint32_t& r0, uint32_t& r1,
                                        uint32_t& r2, uint32_t& r3, uint32_t addr) {
    asm volatile("ldmatrix.sync.aligned.m8n8.x4.shared.b16 {%0,%1,%2,%3}, [%4];"
                 : "=r"(r0), "=r"(r1), "=r"(r2), "=r"(r3) : "r"(addr));
}
__device__ __forceinline__ void ldsm_x4_t(uint32_t& r0, uint32_t& r1,
                                          uint32_t& r2, uint32_t& r3, uint32_t addr) {
    asm volatile("ldmatrix.sync.aligned.m8n8.x4.trans.shared.b16 {%0,%1,%2,%3}, [%4];"
                 : "=r"(r0), "=r"(r1), "=r"(r2), "=r"(r3) : "r"(addr));
}
__device__ __forceinline__ void mma_bf16(float* c, const uint32_t* a, const uint32_t* b) {
    asm volatile(
        "mma.sync.aligned.m16n8k16.row.col.f32.bf16.bf16.f32 "
        "{%0,%1,%2,%3}, {%4,%5,%6,%7}, {%8,%9}, {%0,%1,%2,%3};"
        : "+f"(c[0]), "+f"(c[1]), "+f"(c[2]), "+f"(c[3])
        : "r"(a[0]), "r"(a[1]), "r"(a[2]), "r"(a[3]), "r"(b[0]), "r"(b[1]));
}
__device__ __forceinline__ void mma_f16(float* c, const uint32_t* a, const uint32_t* b) {
    asm volatile(
        "mma.sync.aligned.m16n8k16.row.col.f32.f16.f16.f32 "
        "{%0,%1,%2,%3}, {%4,%5,%6,%7}, {%8,%9}, {%0,%1,%2,%3};"
        : "+f"(c[0]), "+f"(c[1]), "+f"(c[2]), "+f"(c[3])
        : "r"(a[0]), "r"(a[1]), "r"(a[2]), "r"(a[3]), "r"(b[0]), "r"(b[1]));
}

// FMA-only 2^t for t <= ~0 (no MUFU). |err| ~ 1e-7 relative.
__device__ __forceinline__ float exp2s(float t) {
    t = fmaxf(t, -120.0f);
    float z = t + 12582912.0f;                 // round-to-nearest via magic
    int   n = __float_as_int(z) - 0x4B400000;  // integer part
    float r = t - (z - 12582912.0f);           // r in [-0.5, 0.5]
    float p = 1.5403530e-4f;
    p = fmaf(p, r, 1.3333558e-3f);
    p = fmaf(p, r, 9.6181291e-3f);
    p = fmaf(p, r, 5.5504109e-2f);
    p = fmaf(p, r, 2.4022651e-1f);
    p = fmaf(p, r, 6.9314718e-1f);
    p = fmaf(p, r, 1.0f);
    return p * __int_as_float((n + 127) << 23);
}

// ---------------------------------------------------------------------------
// fp32 -> bf16 hi/lo split (x input)
// ---------------------------------------------------------------------------
__global__ void split_f32(const float* __restrict__ in,
                          __nv_bfloat16* __restrict__ h,
                          __nv_bfloat16* __restrict__ l, int n4)
{
    int i = blockIdx.x * blockDim.x + threadIdx.x;
    if (i >= n4) return;
    float4 v = ((const float4*)in)[i];
    __nv_bfloat16 h0 = __float2bfloat16(v.x);
    __nv_bfloat16 h1 = __float2bfloat16(v.y);
    __nv_bfloat16 h2 = __float2bfloat16(v.z);
    __nv_bfloat16 h3 = __float2bfloat16(v.w);
    __nv_bfloat16 l0 = __float2bfloat16(v.x - __bfloat162float(h0));
    __nv_bfloat16 l1 = __float2bfloat16(v.y - __bfloat162float(h1));
    __nv_bfloat16 l2 = __float2bfloat16(v.z - __bfloat162float(h2));
    __nv_bfloat16 l3 = __float2bfloat16(v.w - __bfloat162float(h3));
    ((__nv_bfloat162*)h)[2 * i]     = __halves2bfloat162(h0, h1);
    ((__nv_bfloat162*)h)[2 * i + 1] = __halves2bfloat162(h2, h3);
    ((__nv_bfloat162*)l)[2 * i]     = __halves2bfloat162(l0, l1);
    ((__nv_bfloat162*)l)[2 * i + 1] = __halves2bfloat162(l2, l3);
}

// W[K][N] -> W^T[N][K] bf16 hi/lo via smem tile (coalesced both sides)
__global__ void wsplit_T(const float* __restrict__ W,
                         __nv_bfloat16* __restrict__ hT,
                         __nv_bfloat16* __restrict__ lT)
{
    __shared__ float t[32][33];
    const int tx = threadIdx.x, ty = threadIdx.y;   // 32 x 8
    const int n0 = blockIdx.x * 32, k0 = blockIdx.y * 32;
#pragma unroll
    for (int i = 0; i < 4; i++)
        t[ty + i * 8][tx] = W[(size_t)(k0 + ty + i * 8) * 1024 + n0 + tx];
    __syncthreads();
#pragma unroll
    for (int i = 0; i < 4; i++) {
        int nl = ty + i * 8;
        float v = t[tx][nl];
        __nv_bfloat16 h = __float2bfloat16(v);
        __nv_bfloat16 l = __float2bfloat16(v - __bfloat162float(h));
        hT[(size_t)(n0 + nl) * 1024 + k0 + tx] = h;
        lT[(size_t)(n0 + nl) * 1024 + k0 + tx] = l;
    }
}

// ---------------------------------------------------------------------------
// Tensor-core GEMM (mma.sync bf16, fp32-split 3-pass): C = A @ BT^T + bias
// MODE 0: fp32 out; MODE 1: bf16 hi/lo out (scaled); MODE 2: fp16 out.
// 128x128 CTA tile, BK=64, 256 threads, warp grid 2x4 (warp tile 64x32).
// ---------------------------------------------------------------------------
template<int MODE>
__global__ __launch_bounds__(256, 2)
void gemm_bf16_mma(const __nv_bfloat16* __restrict__ Ah,
                   const __nv_bfloat16* __restrict__ Al,
                   const __nv_bfloat16* __restrict__ BTh,
                   const __nv_bfloat16* __restrict__ BTl,
                   const float* __restrict__ bias,
                   float* __restrict__ Cf,
                   __nv_bfloat16* __restrict__ Ch,
                   __nv_bfloat16* __restrict__ Cl,
                   __half* __restrict__ Cx,
                   float scale)
{
    extern __shared__ char smem_raw[];
    const uint32_t sb0  = (smem_u32(smem_raw) + 1023u) & ~1023u;
    const uint32_t SA_H = sb0;
    const uint32_t SA_L = sb0 + 16384;
    const uint32_t SB_H = sb0 + 32768;
    const uint32_t SB_L = sb0 + 49152;

    const int tid = threadIdx.x, wid = tid >> 5, lid = tid & 31;
    const int bx = blockIdx.x, by = blockIdx.y;
    const int wm = wid >> 2;
    const int wn = wid & 3;

    const __nv_bfloat16* aH = Ah  + (size_t)(by * 128) * 1024;
    const __nv_bfloat16* aL = Al  + (size_t)(by * 128) * 1024;
    const __nv_bfloat16* bH = BTh + (size_t)(bx * 128) * 1024;
    const __nv_bfloat16* bL = BTl + (size_t)(bx * 128) * 1024;

    float acc[4][4][4];
#pragma unroll
    for (int i = 0; i < 4; i++)
#pragma unroll
        for (int j = 0; j < 4; j++)
#pragma unroll
            for (int t = 0; t < 4; t++) acc[i][j][t] = 0.0f;

    const int a_row_l = (lid & 15);
    const int a_cb_l  = (lid >> 4) << 4;
    const int b_row_l = (lid & 7);
    const int b_grp   = lid >> 3;

    for (int kc = 0; kc < 16; kc++) {
        __syncthreads();
#pragma unroll
        for (int i = 0; i < 4; i++) {
            int g = tid + i * 256;
            int row = g >> 3, c16 = g & 7;
            uint32_t soff = SMEM_SWIZZLE_128B((uint32_t)(row * 128 + c16 * 16));
            size_t goff = (size_t)row * 1024 + (size_t)kc * 64 + c16 * 8;
            CP_ASYNC16(SA_H + soff, aH + goff);
            CP_ASYNC16(SA_L + soff, aL + goff);
            CP_ASYNC16(SB_H + soff, bH + goff);
            CP_ASYNC16(SB_L + soff, bL + goff);
        }
        CP_COMMIT();
        CP_WAIT0();
        __syncthreads();

#pragma unroll
        for (int ks = 0; ks < 4; ks++) {
            // B_H fragments: warp n-tile = 32 cols = 4 n-blocks = 2 x4-loads
            uint32_t bh[2][4];
#pragma unroll
            for (int np = 0; np < 2; np++) {
                uint32_t off = (uint32_t)((wn * 32 + (2 * np + (b_grp >> 1)) * 8 + b_row_l) * 128
                                          + ks * 32 + (b_grp & 1) * 16);
                ldsm_x4(bh[np][0], bh[np][1], bh[np][2], bh[np][3],
                        SB_H + SMEM_SWIZZLE_128B(off));
            }
            uint32_t aH4[4], aL4[4];
#pragma unroll
            for (int mf = 0; mf < 4; mf++) {
                uint32_t offh = (uint32_t)((wm * 64 + mf * 16 + a_row_l) * 128
                                           + ks * 32 + a_cb_l);
                ldsm_x4(aH4[0], aH4[1], aH4[2], aH4[3], SA_H + SMEM_SWIZZLE_128B(offh));
                ldsm_x4(aL4[0], aL4[1], aL4[2], aL4[3], SA_L + SMEM_SWIZZLE_128B(offh));
#pragma unroll
                for (int np = 0; np < 2; np++) {
                    mma_bf16(acc[mf][2 * np],     aH4, &bh[np][0]);
                    mma_bf16(acc[mf][2 * np + 1], aH4, &bh[np][2]);
                    mma_bf16(acc[mf][2 * np],     aL4, &bh[np][0]);
                    mma_bf16(acc[mf][2 * np + 1], aL4, &bh[np][2]);
                }
            }
            // B_L fragments, A_H only
            uint32_t bl[2][4];
#pragma unroll
            for (int np = 0; np < 2; np++) {
                uint32_t off = (uint32_t)((wn * 32 + (2 * np + (b_grp >> 1)) * 8 + b_row_l) * 128
                                          + ks * 32 + (b_grp & 1) * 16);
                ldsm_x4(bl[np][0], bl[np][1], bl[np][2], bl[np][3],
                        SB_L + SMEM_SWIZZLE_128B(off));
            }
#pragma unroll
            for (int mf = 0; mf < 4; mf++) {
                uint32_t offh = (uint32_t)((wm * 64 + mf * 16 + a_row_l) * 128
                                           + ks * 32 + a_cb_l);
                ldsm_x4(aH4[0], aH4[1], aH4[2], aH4[3], SA_H + SMEM_SWIZZLE_128B(offh));
#pragma unroll
                for (int np = 0; np < 2; np++) {
                    mma_bf16(acc[mf][2 * np],     aH4, &bl[np][0]);
                    mma_bf16(acc[mf][2 * np + 1], aH4, &bl[np][2]);
                }
            }
        }
    }

    // epilogue
    const int er = lid >> 2;
    const int ec = (lid & 3) << 1;
#pragma unroll
    for (int mf = 0; mf < 4; mf++) {
#pragma unroll
        for (int nf = 0; nf < 4; nf++) {
            const int m = by * 128 + wm * 64 + mf * 16 + er;
            const int n = bx * 128 + wn * 32 + nf * 8 + ec;
            float2 bv = *(const float2*)&bias[n];
            float v00 = (acc[mf][nf][0] + bv.x) * scale;
            float v01 = (acc[mf][nf][1] + bv.y) * scale;
            float v10 = (acc[mf][nf][2] + bv.x) * scale;
            float v11 = (acc[mf][nf][3] + bv.y) * scale;
            if (MODE == 0) {
                *(float2*)&Cf[(size_t)m * 1024 + n]       = make_float2(v00, v01);
                *(float2*)&Cf[(size_t)(m + 8) * 1024 + n] = make_float2(v10, v11);
            } else if (MODE == 1) {
                __nv_bfloat16 h00 = __float2bfloat16(v00), h01 = __float2bfloat16(v01);
                __nv_bfloat16 h10 = __float2bfloat16(v10), h11 = __float2bfloat16(v11);
                *(__nv_bfloat162*)&Ch[(size_t)m * 1024 + n] = __halves2bfloat162(h00, h01);
                *(__nv_bfloat162*)&Ch[(size_t)(m + 8) * 1024 + n] = __halves2bfloat162(h10, h11);
                *(__nv_bfloat162*)&Cl[(size_t)m * 1024 + n] =
                    __halves2bfloat162(__float2bfloat16(v00 - __bfloat162float(h00)),
                                       __float2bfloat16(v01 - __bfloat162float(h01)));
                *(__nv_bfloat162*)&Cl[(size_t)(m + 8) * 1024 + n] =
                    __halves2bfloat162(__float2bfloat16(v10 - __bfloat162float(h10)),
                                       __float2bfloat16(v11 - __bfloat162float(h11)));
            } else {
                *(__half2*)&Cx[(size_t)m * 1024 + n]       = __floats2half2_rn(v00, v01);
                *(__half2*)&Cx[(size_t)(m + 8) * 1024 + n] = __floats2half2_rn(v10, v11);
            }
        }
    }
}

// ---------------------------------------------------------------------------
// Tensor-core causal flash attention.
// CTA = (q-tile 128, head, batch); 8 warps, warp owns 16 q-rows x 128 k-cols.
// S via 3-pass bf16 hi/lo mma; softmax base-2 with FMA-only exp2; PV fp16 mma.
// Output written bf16 hi/lo (feeds the final GEMM directly).
// ---------------------------------------------------------------------------
__global__ __launch_bounds__(256)
void flash_attn_tc(const __nv_bfloat16* __restrict__ Qh,
                   const __nv_bfloat16* __restrict__ Ql,
                   const __nv_bfloat16* __restrict__ Kh,
                   const __nv_bfloat16* __restrict__ Kl,
                   const __half* __restrict__ V16,
                   __nv_bfloat16* __restrict__ Oh,
                   __nv_bfloat16* __restrict__ Ol)
{
    extern __shared__ char smem_raw[];
    const uint32_t sb0  = (smem_u32(smem_raw) + 1023u) & ~1023u;
    const uint32_t SQ_H = sb0;
    const uint32_t SQ_L = sb0 + 16384;
    const uint32_t SK_H = sb0 + 32768;
    const uint32_t SK_L = sb0 + 49152;
    const uint32_t SV   = sb0 + 65536;

    const int tid = threadIdx.x, wid = tid >> 5, lid = tid & 31;
    const int qi = blockIdx.x;          // q-tile (128 rows)
    const int h  = blockIdx.y;
    const int b  = blockIdx.z;
    const int q0 = qi * 128;
    const size_t rbase = (size_t)b * SEQ;   // row base
    const int    cbase = h * 64;            // column base in [.,1024]

    const int a_row_l = (lid & 15);
    const int a_cb_l  = (lid >> 4) << 4;
    const int b_row_l = (lid & 7);
    const int b_grp   = lid >> 3;

    // Q tile load (once)
#pragma unroll
    for (int i = 0; i < 4; i++) {
        int g = tid + i * 256;
        int row = g >> 3, c16 = g & 7;
        uint32_t soff = SMEM_SWIZZLE_128B((uint32_t)(row * 128 + c16 * 16));
        size_t goff = (rbase + q0 + row) * 1024 + cbase + c16 * 8;
        CP_ASYNC16(SQ_H + soff, Qh + goff);
        CP_ASYNC16(SQ_L + soff, Ql + goff);
    }
    CP_COMMIT();

    float m[2] = {-1e30f, -1e30f};
    float l[2] = {0.0f, 0.0f};
    float o[8][4];
#pragma unroll
    for (int i = 0; i < 8; i++)
#pragma unroll
        for (int j = 0; j < 4; j++) o[i][j] = 0.0f;

    for (int kt = 0; kt <= qi; kt++) {
        if (kt > 0) __syncthreads();
#pragma unroll
        for (int i = 0; i < 4; i++) {
            int g = tid + i * 256;
            int row = g >> 3, c16 = g & 7;
            uint32_t soff = SMEM_SWIZZLE_128B((uint32_t)(row * 128 + c16 * 16));
            size_t goff = (rbase + kt * 128 + row) * 1024 + cbase + c16 * 8;
            CP_ASYNC16(SK_H + soff, Kh + goff);
            CP_ASYNC16(SK_L + soff, Kl + goff);
            CP_ASYNC16(SV   + soff, V16 + goff);
        }
        CP_COMMIT();
        CP_WAIT0();
        __syncthreads();

        // ---- S = Q K^T (3-pass hi/lo) ----
        float s[16][4];
#pragma unroll
        for (int nf = 0; nf < 16; nf++)
#pragma unroll
            for (int c = 0; c < 4; c++) s[nf][c] = 0.0f;

#pragma unroll
        for (int ks = 0; ks < 4; ks++) {
            const uint32_t a_off =
                SMEM_SWIZZLE_128B((uint32_t)((wid * 16 + a_row_l) * 128 + ks * 32 + a_cb_l));
            uint32_t aH4[4], aL4[4];
            ldsm_x4(aH4[0], aH4[1], aH4[2], aH4[3], SQ_H + a_off);
            ldsm_x4(aL4[0], aL4[1], aL4[2], aL4[3], SQ_L + a_off);
#pragma unroll
            for (int np = 0; np < 8; np++) {
                uint32_t off = SMEM_SWIZZLE_128B(
                    (uint32_t)(((2 * np + (b_grp >> 1)) * 8 + b_row_l) * 128
                               + ks * 32 + (b_grp & 1) * 16));
                uint32_t bb[4];
                ldsm_x4(bb[0], bb[1], bb[2], bb[3], SK_H + off);
                mma_bf16(s[2 * np],     aH4, &bb[0]);
                mma_bf16(s[2 * np + 1], aH4, &bb[2]);
                mma_bf16(s[2 * np],     aL4, &bb[0]);
                mma_bf16(s[2 * np + 1], aL4, &bb[2]);
                ldsm_x4(bb[0], bb[1], bb[2], bb[3], SK_L + off);
                mma_bf16(s[2 * np],     aH4, &bb[0]);
                mma_bf16(s[2 * np + 1], aH4, &bb[2]);
            }
        }

        // ---- causal mask on diagonal tile ----
        if (kt == qi) {
            const int rl0 = wid * 16 + (lid >> 2);
#pragma unroll
            for (int nf = 0; nf < 16; nf++) {
                const int cl = nf * 8 + ((lid & 3) << 1);
#pragma unroll
                for (int c = 0; c < 4; c++) {
                    const int row = rl0 + ((c >> 1) << 3);
                    const int col = cl + (c & 1);
                    if (col > row) s[nf][c] = -1e30f;
                }
            }
        }

        // ---- online softmax (base-2 domain), FMA-only exp ----
        uint32_t ph[16][2];
#pragma unroll
        for (int rs = 0; rs < 2; rs++) {
            const int ci = rs << 1;
            float mt = -1e30f;
#pragma unroll
            for (int nf = 0; nf < 16; nf++)
                mt = fmaxf(mt, fmaxf(s[nf][ci], s[nf][ci + 1]));
            mt = fmaxf(mt, __shfl_xor_sync(0xffffffffu, mt, 1));
            mt = fmaxf(mt, __shfl_xor_sync(0xffffffffu, mt, 2));
            const float mn = fmaxf(m[rs], mt);
            const float alpha = exp2s(m[rs] - mn);
            m[rs] = mn;
            float rsum = 0.0f;
#pragma unroll
            for (int nf = 0; nf < 16; nf++) {
                float p0 = exp2s(s[nf][ci] - mn);
                float p1 = exp2s(s[nf][ci + 1] - mn);
                s[nf][ci] = p0;
                s[nf][ci + 1] = p1;
                rsum += p0 + p1;
            }
            rsum += __shfl_xor_sync(0xffffffffu, rsum, 1);
            rsum += __shfl_xor_sync(0xffffffffu, rsum, 2);
            l[rs] = l[rs] * alpha + rsum;
#pragma unroll
            for (int df = 0; df < 8; df++) {
                o[df][ci] *= alpha;
                o[df][ci + 1] *= alpha;
            }
        }
#pragma unroll
        for (int nf = 0; nf < 16; nf++) {
            __half2 p0 = __floats2half2_rn(s[nf][0], s[nf][1]);
            __half2 p1 = __floats2half2_rn(s[nf][2], s[nf][3]);
            ph[nf][0] = *(uint32_t*)&p0;
            ph[nf][1] = *(uint32_t*)&p1;
        }

        // ---- O += P V (fp16 mma, V via ldmatrix.trans) ----
#pragma unroll
        for (int j = 0; j < 8; j++) {
            uint32_t A4[4] = { ph[2 * j][0], ph[2 * j][1],
                               ph[2 * j + 1][0], ph[2 * j + 1][1] };
#pragma unroll
            for (int dp = 0; dp < 4; dp++) {
                uint32_t off = SMEM_SWIZZLE_128B(
                    (uint32_t)((j * 16 + (b_grp & 1) * 8 + b_row_l) * 128
                               + dp * 32 + (b_grp >> 1) * 16));
                uint32_t bb[4];
                ldsm_x4_t(bb[0], bb[1], bb[2], bb[3], SV + off);
                mma_f16(o[2 * dp],     A4, &bb[0]);
                mma_f16(o[2 * dp + 1], A4, &bb[2]);
            }
        }
    }

    // ---- epilogue: normalize, split bf16 hi/lo ----
    const float inv0 = 1.0f / l[0];
    const float inv1 = 1.0f / l[1];
    const int er = lid >> 2;
    const int ec = (lid & 3) << 1;
#pragma unroll
    for (int df = 0; df < 8; df++) {
        const int n = cbase + df * 8 + ec;
#pragma unroll
        for (int rs = 0; rs < 2; rs++) {
            const float inv = rs ? inv1 : inv0;
            const size_t row = rbase + q0 + wid * 16 + er + rs * 8;
            float v0 = o[df][2 * rs] * inv;
            float v1 = o[df][2 * rs + 1] * inv;
            __nv_bfloat16 h0 = __float2bfloat16(v0);
            __nv_bfloat16 h1 = __float2bfloat16(v1);
            *(__nv_bfloat162*)&Oh[row * 1024 + n] = __halves2bfloat162(h0, h1);
            *(__nv_bfloat162*)&Ol[row * 1024 + n] =
                __halves2bfloat162(__float2bfloat16(v0 - __bfloat162float(h0)),
                                   __float2bfloat16(v1 - __bfloat162float(h1)));
        }
    }
}

// ---------------------------------------------------------------------------
extern "C" void kernel_launch(void* const* d_in, const int* in_sizes, int n_in,
                              void* d_out, int out_size)
{
    (void)in_sizes; (void)n_in; (void)out_size;
    const float* x  = (const float*)d_in[0];
    const float* Wq = (const float*)d_in[1];
    const float* bq = (const float*)d_in[2];
    const float* Wk = (const float*)d_in[3];
    const float* bk = (const float*)d_in[4];
    const float* Wv = (const float*)d_in[5];
    const float* bv = (const float*)d_in[6];
    const float* Wo = (const float*)d_in[7];
    const float* bo = (const float*)d_in[8];
    float* out = (float*)d_out;

    __nv_bfloat16 *xh, *xl, *qh, *ql, *kh, *kl, *wth, *wtl;
    __half *v16;
    cudaGetSymbolAddress((void**)&xh, g_xh);
    cudaGetSymbolAddress((void**)&xl, g_xl);
    cudaGetSymbolAddress((void**)&qh, g_qh);
    cudaGetSymbolAddress((void**)&ql, g_ql);
    cudaGetSymbolAddress((void**)&kh, g_kh);
    cudaGetSymbolAddress((void**)&kl, g_kl);
    cudaGetSymbolAddress((void**)&v16, g_v16);
    cudaGetSymbolAddress((void**)&wth, g_wth);
    cudaGetSymbolAddress((void**)&wtl, g_wtl);

    const size_t WSZ = (size_t)D_MODEL * D_MODEL;
    const int GEMM_SMEM = 66560;
    const int FLASH_SMEM = 83968;
    cudaFuncSetAttribute(gemm_bf16_mma<0>, cudaFuncAttributeMaxDynamicSharedMemorySize, GEMM_SMEM);
    cudaFuncSetAttribute(gemm_bf16_mma<1>, cudaFuncAttributeMaxDynamicSharedMemorySize, GEMM_SMEM);
    cudaFuncSetAttribute(gemm_bf16_mma<2>, cudaFuncAttributeMaxDynamicSharedMemorySize, GEMM_SMEM);
    cudaFuncSetAttribute(flash_attn_tc, cudaFuncAttributeMaxDynamicSharedMemorySize, FLASH_SMEM);

    // input split + weight transpose-splits
    split_f32<<<(MROWS * D_MODEL / 4 + 255) / 256, 256>>>(x, xh, xl, MROWS * D_MODEL / 4);
    dim3 wt(32, 32);
    dim3 wtb(32, 8);
    wsplit_T<<<wt, wtb>>>(Wq, wth + 0 * WSZ, wtl + 0 * WSZ);
    wsplit_T<<<wt, wtb>>>(Wk, wth + 1 * WSZ, wtl + 1 * WSZ);
    wsplit_T<<<wt, wtb>>>(Wv, wth + 2 * WSZ, wtl + 2 * WSZ);
    wsplit_T<<<wt, wtb>>>(Wo, wth + 3 * WSZ, wtl + 3 * WSZ);

    dim3 gg(D_MODEL / 128, MROWS / 128);   // (8, 64)
    gemm_bf16_mma<1><<<gg, 256, GEMM_SMEM>>>(xh, xl, wth + 0 * WSZ, wtl + 0 * WSZ,
                                             bq, nullptr, qh, ql, nullptr, QSCALE);
    gemm_bf16_mma<1><<<gg, 256, GEMM_SMEM>>>(xh, xl, wth + 1 * WSZ, wtl + 1 * WSZ,
                                             bk, nullptr, kh, kl, nullptr, 1.0f);
    gemm_bf16_mma<2><<<gg, 256, GEMM_SMEM>>>(xh, xl, wth + 2 * WSZ, wtl + 2 * WSZ,
                                             bv, nullptr, nullptr, nullptr, v16, 1.0f);

    dim3 ga(SEQ / 128, NHEADS, BATCH);     // (16, 16, 4)
    flash_attn_tc<<<ga, 256, FLASH_SMEM>>>(qh, ql, kh, kl, v16, xh, xl);

    gemm_bf16_mma<0><<<gg, 256, GEMM_SMEM>>>(xh, xl, wth + 3 * WSZ, wtl + 3 * WSZ,
                                             bo, out, nullptr, nullptr, nullptr, 1.0f);
}

// round 6
// speedup vs baseline: 4.0722x; 1.1097x over previous
#include <cuda_runtime.h>
#include <cuda_bf16.h>
#include <cuda_fp16.h>
#include <math_constants.h>
#include <cstdint>

#define D_MODEL 1024
#define NHEADS 16
#define DK 64
#define BATCH 4
#define SEQ 2048
#define MROWS (BATCH * SEQ)   // 8192

// fold 1/sqrt(dk) * log2(e) into Q so softmax runs in base-2 domain
#define QSCALE 0.18033688011112042f

// ---------------------------------------------------------------------------
// Scratch (allocation-free rule: __device__ globals)
// ---------------------------------------------------------------------------
__device__ __nv_bfloat16 g_xh[(size_t)MROWS * D_MODEL];
__device__ __nv_bfloat16 g_xl[(size_t)MROWS * D_MODEL];
__device__ __nv_bfloat16 g_qh[(size_t)MROWS * D_MODEL];
__device__ __nv_bfloat16 g_ql[(size_t)MROWS * D_MODEL];
__device__ __nv_bfloat16 g_kh[(size_t)MROWS * D_MODEL];
__device__ __nv_bfloat16 g_kl[(size_t)MROWS * D_MODEL];
__device__ __half        g_v16[(size_t)MROWS * D_MODEL];
// transposed weights [N][K] hi/lo; [0..2] = Wq,Wk,Wv packed (fused GEMM), [3]=Wo
__device__ __nv_bfloat16 g_wth[4][(size_t)D_MODEL * D_MODEL];
__device__ __nv_bfloat16 g_wtl[4][(size_t)D_MODEL * D_MODEL];

// ---------------------------------------------------------------------------
// helpers (base-target PTX only: cp.async / ldmatrix / mma.sync)
// ---------------------------------------------------------------------------
__device__ __forceinline__ uint32_t smem_u32(const void* p) {
    uint32_t a;
    asm("{ .reg .u64 t; cvta.to.shared.u64 t, %1; cvt.u32.u64 %0, t; }"
        : "=r"(a) : "l"(p));
    return a;
}
#define SMEM_SWIZZLE_128B(off) ((off) ^ (((off) >> 3) & 0x70))

#define CP_ASYNC16(dst, src) \
    asm volatile("cp.async.cg.shared.global [%0], [%1], 16;" \
                 :: "r"((uint32_t)(dst)), "l"(src) : "memory")
#define CP_COMMIT() asm volatile("cp.async.commit_group;" ::: "memory")
#define CP_WAIT0()  asm volatile("cp.async.wait_group 0;" ::: "memory")
#define CP_WAIT1()  asm volatile("cp.async.wait_group 1;" ::: "memory")

__device__ __forceinline__ void ldsm_x4(uint32_t& r0, uint32_t& r1,
                                        uint32_t& r2, uint32_t& r3, uint32_t addr) {
    asm volatile("ldmatrix.sync.aligned.m8n8.x4.shared.b16 {%0,%1,%2,%3}, [%4];"
                 : "=r"(r0), "=r"(r1), "=r"(r2), "=r"(r3) : "r"(addr));
}
__device__ __forceinline__ void ldsm_x4_t(uint32_t& r0, uint32_t& r1,
                                          uint32_t& r2, uint32_t& r3, uint32_t addr) {
    asm volatile("ldmatrix.sync.aligned.m8n8.x4.trans.shared.b16 {%0,%1,%2,%3}, [%4];"
                 : "=r"(r0), "=r"(r1), "=r"(r2), "=r"(r3) : "r"(addr));
}
__device__ __forceinline__ void mma_bf16(float* c, const uint32_t* a, const uint32_t* b) {
    asm volatile(
        "mma.sync.aligned.m16n8k16.row.col.f32.bf16.bf16.f32 "
        "{%0,%1,%2,%3}, {%4,%5,%6,%7}, {%8,%9}, {%0,%1,%2,%3};"
        : "+f"(c[0]), "+f"(c[1]), "+f"(c[2]), "+f"(c[3])
        : "r"(a[0]), "r"(a[1]), "r"(a[2]), "r"(a[3]), "r"(b[0]), "r"(b[1]));
}
__device__ __forceinline__ void mma_f16(float* c, const uint32_t* a, const uint32_t* b) {
    asm volatile(
        "mma.sync.aligned.m16n8k16.row.col.f32.f16.f16.f32 "
        "{%0,%1,%2,%3}, {%4,%5,%6,%7}, {%8,%9}, {%0,%1,%2,%3};"
        : "+f"(c[0]), "+f"(c[1]), "+f"(c[2]), "+f"(c[3])
        : "r"(a[0]), "r"(a[1]), "r"(a[2]), "r"(a[3]), "r"(b[0]), "r"(b[1]));
}

// FMA-only 2^t for t <= ~0 (no MUFU). |err| ~ 1e-7 relative.
__device__ __forceinline__ float exp2s(float t) {
    t = fmaxf(t, -120.0f);
    float z = t + 12582912.0f;
    int   n = __float_as_int(z) - 0x4B400000;
    float r = t - (z - 12582912.0f);
    float p = 1.5403530e-4f;
    p = fmaf(p, r, 1.3333558e-3f);
    p = fmaf(p, r, 9.6181291e-3f);
    p = fmaf(p, r, 5.5504109e-2f);
    p = fmaf(p, r, 2.4022651e-1f);
    p = fmaf(p, r, 6.9314718e-1f);
    p = fmaf(p, r, 1.0f);
    return p * __int_as_float((n + 127) << 23);
}

// ---------------------------------------------------------------------------
// fp32 -> bf16 hi/lo split (x input)
// ---------------------------------------------------------------------------
__global__ void split_f32(const float* __restrict__ in,
                          __nv_bfloat16* __restrict__ h,
                          __nv_bfloat16* __restrict__ l, int n4)
{
    int i = blockIdx.x * blockDim.x + threadIdx.x;
    if (i >= n4) return;
    float4 v = ((const float4*)in)[i];
    __nv_bfloat16 h0 = __float2bfloat16(v.x);
    __nv_bfloat16 h1 = __float2bfloat16(v.y);
    __nv_bfloat16 h2 = __float2bfloat16(v.z);
    __nv_bfloat16 h3 = __float2bfloat16(v.w);
    __nv_bfloat16 l0 = __float2bfloat16(v.x - __bfloat162float(h0));
    __nv_bfloat16 l1 = __float2bfloat16(v.y - __bfloat162float(h1));
    __nv_bfloat16 l2 = __float2bfloat16(v.z - __bfloat162float(h2));
    __nv_bfloat16 l3 = __float2bfloat16(v.w - __bfloat162float(h3));
    ((__nv_bfloat162*)h)[2 * i]     = __halves2bfloat162(h0, h1);
    ((__nv_bfloat162*)h)[2 * i + 1] = __halves2bfloat162(h2, h3);
    ((__nv_bfloat162*)l)[2 * i]     = __halves2bfloat162(l0, l1);
    ((__nv_bfloat162*)l)[2 * i + 1] = __halves2bfloat162(l2, l3);
}

// W[K][N] -> W^T[N][K] bf16 hi/lo via smem tile (coalesced both sides)
__global__ void wsplit_T(const float* __restrict__ W,
                         __nv_bfloat16* __restrict__ hT,
                         __nv_bfloat16* __restrict__ lT)
{
    __shared__ float t[32][33];
    const int tx = threadIdx.x, ty = threadIdx.y;   // 32 x 8
    const int n0 = blockIdx.x * 32, k0 = blockIdx.y * 32;
#pragma unroll
    for (int i = 0; i < 4; i++)
        t[ty + i * 8][tx] = W[(size_t)(k0 + ty + i * 8) * 1024 + n0 + tx];
    __syncthreads();
#pragma unroll
    for (int i = 0; i < 4; i++) {
        int nl = ty + i * 8;
        float v = t[tx][nl];
        __nv_bfloat16 h = __float2bfloat16(v);
        __nv_bfloat16 l = __float2bfloat16(v - __bfloat162float(h));
        hT[(size_t)(n0 + nl) * 1024 + k0 + tx] = h;
        lT[(size_t)(n0 + nl) * 1024 + k0 + tx] = l;
    }
}

// ---------------------------------------------------------------------------
// Shared GEMM mainloop: acc += A(128xK) @ BT(128xK)^T, 3-pass bf16 hi/lo.
// Restructured: all fragments loaded once per k-step (no redundant A_H ldsm).
// ---------------------------------------------------------------------------
struct GemmCtx {
    uint32_t SA_H, SA_L, SB_H, SB_L;
    int a_row_l, a_cb_l, b_row_l, b_grp, wm, wn;
};

__device__ __forceinline__ void gemm_mainloop(
    const GemmCtx& g,
    const __nv_bfloat16* aH, const __nv_bfloat16* aL,
    const __nv_bfloat16* bH, const __nv_bfloat16* bL,
    int tid, float acc[4][4][4])
{
    for (int kc = 0; kc < 16; kc++) {
        __syncthreads();
#pragma unroll
        for (int i = 0; i < 4; i++) {
            int gg = tid + i * 256;
            int row = gg >> 3, c16 = gg & 7;
            uint32_t soff = SMEM_SWIZZLE_128B((uint32_t)(row * 128 + c16 * 16));
            size_t goff = (size_t)row * 1024 + (size_t)kc * 64 + c16 * 8;
            CP_ASYNC16(g.SA_H + soff, aH + goff);
            CP_ASYNC16(g.SA_L + soff, aL + goff);
            CP_ASYNC16(g.SB_H + soff, bH + goff);
            CP_ASYNC16(g.SB_L + soff, bL + goff);
        }
        CP_COMMIT();
        CP_WAIT0();
        __syncthreads();

#pragma unroll
        for (int ks = 0; ks < 4; ks++) {
            uint32_t bh[2][4], bl[2][4];
#pragma unroll
            for (int np = 0; np < 2; np++) {
                uint32_t off = SMEM_SWIZZLE_128B(
                    (uint32_t)((g.wn * 32 + (2 * np + (g.b_grp >> 1)) * 8 + g.b_row_l) * 128
                               + ks * 32 + (g.b_grp & 1) * 16));
                ldsm_x4(bh[np][0], bh[np][1], bh[np][2], bh[np][3], g.SB_H + off);
                ldsm_x4(bl[np][0], bl[np][1], bl[np][2], bl[np][3], g.SB_L + off);
            }
#pragma unroll
            for (int mf = 0; mf < 4; mf++) {
                uint32_t offh = SMEM_SWIZZLE_128B(
                    (uint32_t)((g.wm * 64 + mf * 16 + g.a_row_l) * 128
                               + ks * 32 + g.a_cb_l));
                uint32_t aH4[4], aL4[4];
                ldsm_x4(aH4[0], aH4[1], aH4[2], aH4[3], g.SA_H + offh);
                ldsm_x4(aL4[0], aL4[1], aL4[2], aL4[3], g.SA_L + offh);
#pragma unroll
                for (int np = 0; np < 2; np++) {
                    mma_bf16(acc[mf][2 * np],     aH4, &bh[np][0]);
                    mma_bf16(acc[mf][2 * np + 1], aH4, &bh[np][2]);
                    mma_bf16(acc[mf][2 * np],     aL4, &bh[np][0]);
                    mma_bf16(acc[mf][2 * np + 1], aL4, &bh[np][2]);
                    mma_bf16(acc[mf][2 * np],     aH4, &bl[np][0]);
                    mma_bf16(acc[mf][2 * np + 1], aH4, &bl[np][2]);
                }
            }
        }
    }
}

__device__ __forceinline__ void gemm_ctx_init(GemmCtx& g, uint32_t sb0, int tid) {
    g.SA_H = sb0;
    g.SA_L = sb0 + 16384;
    g.SB_H = sb0 + 32768;
    g.SB_L = sb0 + 49152;
    const int lid = tid & 31, wid = tid >> 5;
    g.wm = wid >> 2;
    g.wn = wid & 3;
    g.a_row_l = lid & 15;
    g.a_cb_l  = (lid >> 4) << 4;
    g.b_row_l = lid & 7;
    g.b_grp   = lid >> 3;
}

// ---------------------------------------------------------------------------
// Fused QKV projection GEMM. grid (24, 64): bx 0-7 -> Q, 8-15 -> K, 16-23 -> V.
// Weights packed contiguously in g_wth/g_wtl[0..2].
// ---------------------------------------------------------------------------
__global__ __launch_bounds__(256, 2)
void gemm_qkv(const __nv_bfloat16* __restrict__ Ah,
              const __nv_bfloat16* __restrict__ Al,
              const __nv_bfloat16* __restrict__ WTh,
              const __nv_bfloat16* __restrict__ WTl,
              const float* __restrict__ bq,
              const float* __restrict__ bk,
              const float* __restrict__ bv,
              __nv_bfloat16* __restrict__ Qh, __nv_bfloat16* __restrict__ Ql,
              __nv_bfloat16* __restrict__ Kh, __nv_bfloat16* __restrict__ Kl,
              __half* __restrict__ V16)
{
    extern __shared__ char smem_raw[];
    const uint32_t sb0 = (smem_u32(smem_raw) + 1023u) & ~1023u;
    const int tid = threadIdx.x, lid = tid & 31;
    const int bx = blockIdx.x, by = blockIdx.y;
    GemmCtx g;
    gemm_ctx_init(g, sb0, tid);

    float acc[4][4][4];
#pragma unroll
    for (int i = 0; i < 4; i++)
#pragma unroll
        for (int j = 0; j < 4; j++)
#pragma unroll
            for (int t = 0; t < 4; t++) acc[i][j][t] = 0.0f;

    gemm_mainloop(g,
                  Ah + (size_t)(by * 128) * 1024,
                  Al + (size_t)(by * 128) * 1024,
                  WTh + (size_t)(bx * 128) * 1024,
                  WTl + (size_t)(bx * 128) * 1024,
                  tid, acc);

    const int proj = bx >> 3;        // 0=Q 1=K 2=V
    const int nb   = bx & 7;
    const float* bias = (proj == 0) ? bq : (proj == 1) ? bk : bv;
    const float scale = (proj == 0) ? QSCALE : 1.0f;

    const int er = lid >> 2;
    const int ec = (lid & 3) << 1;
#pragma unroll
    for (int mf = 0; mf < 4; mf++) {
#pragma unroll
        for (int nf = 0; nf < 4; nf++) {
            const int m = by * 128 + g.wm * 64 + mf * 16 + er;
            const int n = nb * 128 + g.wn * 32 + nf * 8 + ec;
            float2 bvv = *(const float2*)&bias[n];
            float v00 = (acc[mf][nf][0] + bvv.x) * scale;
            float v01 = (acc[mf][nf][1] + bvv.y) * scale;
            float v10 = (acc[mf][nf][2] + bvv.x) * scale;
            float v11 = (acc[mf][nf][3] + bvv.y) * scale;
            if (proj == 2) {
                *(__half2*)&V16[(size_t)m * 1024 + n]       = __floats2half2_rn(v00, v01);
                *(__half2*)&V16[(size_t)(m + 8) * 1024 + n] = __floats2half2_rn(v10, v11);
            } else {
                __nv_bfloat16* Ch = (proj == 0) ? Qh : Kh;
                __nv_bfloat16* Cl = (proj == 0) ? Ql : Kl;
                __nv_bfloat16 h00 = __float2bfloat16(v00), h01 = __float2bfloat16(v01);
                __nv_bfloat16 h10 = __float2bfloat16(v10), h11 = __float2bfloat16(v11);
                *(__nv_bfloat162*)&Ch[(size_t)m * 1024 + n] = __halves2bfloat162(h00, h01);
                *(__nv_bfloat162*)&Ch[(size_t)(m + 8) * 1024 + n] = __halves2bfloat162(h10, h11);
                *(__nv_bfloat162*)&Cl[(size_t)m * 1024 + n] =
                    __halves2bfloat162(__float2bfloat16(v00 - __bfloat162float(h00)),
                                       __float2bfloat16(v01 - __bfloat162float(h01)));
                *(__nv_bfloat162*)&Cl[(size_t)(m + 8) * 1024 + n] =
                    __halves2bfloat162(__float2bfloat16(v10 - __bfloat162float(h10)),
                                       __float2bfloat16(v11 - __bfloat162float(h11)));
            }
        }
    }
}

// ---------------------------------------------------------------------------
// Output projection GEMM (fp32 out).
// ---------------------------------------------------------------------------
__global__ __launch_bounds__(256, 2)
void gemm_out(const __nv_bfloat16* __restrict__ Ah,
              const __nv_bfloat16* __restrict__ Al,
              const __nv_bfloat16* __restrict__ WTh,
              const __nv_bfloat16* __restrict__ WTl,
              const float* __restrict__ bias,
              float* __restrict__ C)
{
    extern __shared__ char smem_raw[];
    const uint32_t sb0 = (smem_u32(smem_raw) + 1023u) & ~1023u;
    const int tid = threadIdx.x, lid = tid & 31;
    const int bx = blockIdx.x, by = blockIdx.y;
    GemmCtx g;
    gemm_ctx_init(g, sb0, tid);

    float acc[4][4][4];
#pragma unroll
    for (int i = 0; i < 4; i++)
#pragma unroll
        for (int j = 0; j < 4; j++)
#pragma unroll
            for (int t = 0; t < 4; t++) acc[i][j][t] = 0.0f;

    gemm_mainloop(g,
                  Ah + (size_t)(by * 128) * 1024,
                  Al + (size_t)(by * 128) * 1024,
                  WTh + (size_t)(bx * 128) * 1024,
                  WTl + (size_t)(bx * 128) * 1024,
                  tid, acc);

    const int er = lid >> 2;
    const int ec = (lid & 3) << 1;
#pragma unroll
    for (int mf = 0; mf < 4; mf++) {
#pragma unroll
        for (int nf = 0; nf < 4; nf++) {
            const int m = by * 128 + g.wm * 64 + mf * 16 + er;
            const int n = bx * 128 + g.wn * 32 + nf * 8 + ec;
            float2 bvv = *(const float2*)&bias[n];
            *(float2*)&C[(size_t)m * 1024 + n] =
                make_float2(acc[mf][nf][0] + bvv.x, acc[mf][nf][1] + bvv.y);
            *(float2*)&C[(size_t)(m + 8) * 1024 + n] =
                make_float2(acc[mf][nf][2] + bvv.x, acc[mf][nf][3] + bvv.y);
        }
    }
}

// ---------------------------------------------------------------------------
// Tensor-core causal flash attention, double-buffered K/V prefetch.
// CTA = (q-tile 128, head, batch); 8 warps; S 3-pass bf16 hi/lo; PV fp16.
// ---------------------------------------------------------------------------
__global__ __launch_bounds__(256)
void flash_attn_tc(const __nv_bfloat16* __restrict__ Qh,
                   const __nv_bfloat16* __restrict__ Ql,
                   const __nv_bfloat16* __restrict__ Kh,
                   const __nv_bfloat16* __restrict__ Kl,
                   const __half* __restrict__ V16,
                   __nv_bfloat16* __restrict__ Oh,
                   __nv_bfloat16* __restrict__ Ol)
{
    extern __shared__ char smem_raw[];
    const uint32_t sb0  = (smem_u32(smem_raw) + 1023u) & ~1023u;
    const uint32_t SQ_H = sb0;
    const uint32_t SQ_L = sb0 + 16384;
    const uint32_t STG0 = sb0 + 32768;           // per stage: KH, KL, V (48KB)
    // stage s base = STG0 + s*49152; KH=+0, KL=+16384, V=+32768

    const int tid = threadIdx.x, wid = tid >> 5, lid = tid & 31;
    const int qi = blockIdx.x;
    const int h  = blockIdx.y;
    const int b  = blockIdx.z;
    const int q0 = qi * 128;
    const size_t rbase = (size_t)b * SEQ;
    const int    cbase = h * 64;

    const int a_row_l = (lid & 15);
    const int a_cb_l  = (lid >> 4) << 4;
    const int b_row_l = (lid & 7);
    const int b_grp   = lid >> 3;

    // loader mapping (per thread: 4 x 16B granules per 16KB tile)
    const int l_row0 = tid >> 3;           // +32 per i
    const int l_c16  = tid & 7;

    // prologue: Q + stage 0 (one commit group)
#pragma unroll
    for (int i = 0; i < 4; i++) {
        int row = l_row0 + i * 32;
        uint32_t soff = SMEM_SWIZZLE_128B((uint32_t)(row * 128 + l_c16 * 16));
        size_t goff = (rbase + q0 + row) * 1024 + cbase + l_c16 * 8;
        CP_ASYNC16(SQ_H + soff, Qh + goff);
        CP_ASYNC16(SQ_L + soff, Ql + goff);
        size_t koff = (rbase + row) * 1024 + cbase + l_c16 * 8;
        CP_ASYNC16(STG0 + soff,         Kh + koff);
        CP_ASYNC16(STG0 + 16384 + soff, Kl + koff);
        CP_ASYNC16(STG0 + 32768 + soff, V16 + koff);
    }
    CP_COMMIT();

    float m[2] = {-1e30f, -1e30f};
    float l[2] = {0.0f, 0.0f};
    float o[8][4];
#pragma unroll
    for (int i = 0; i < 8; i++)
#pragma unroll
        for (int j = 0; j < 4; j++) o[i][j] = 0.0f;

    for (int kt = 0; kt <= qi; kt++) {
        const uint32_t SC = STG0 + (uint32_t)(kt & 1) * 49152;   // current stage
        __syncthreads();   // all warps done reading the buffer we're about to refill
        if (kt < qi) {
            const uint32_t SN = STG0 + (uint32_t)((kt + 1) & 1) * 49152;
#pragma unroll
            for (int i = 0; i < 4; i++) {
                int row = l_row0 + i * 32;
                uint32_t soff = SMEM_SWIZZLE_128B((uint32_t)(row * 128 + l_c16 * 16));
                size_t koff = (rbase + (kt + 1) * 128 + row) * 1024 + cbase + l_c16 * 8;
                CP_ASYNC16(SN + soff,         Kh + koff);
                CP_ASYNC16(SN + 16384 + soff, Kl + koff);
                CP_ASYNC16(SN + 32768 + soff, V16 + koff);
            }
            CP_COMMIT();
            CP_WAIT1();    // current stage complete, next still in flight
        } else {
            CP_WAIT0();
        }
        __syncthreads();

        const uint32_t SK_H = SC, SK_L = SC + 16384, SV = SC + 32768;

        // ---- S = Q K^T (3-pass hi/lo) ----
        float s[16][4];
#pragma unroll
        for (int nf = 0; nf < 16; nf++)
#pragma unroll
            for (int c = 0; c < 4; c++) s[nf][c] = 0.0f;

#pragma unroll
        for (int ks = 0; ks < 4; ks++) {
            const uint32_t a_off =
                SMEM_SWIZZLE_128B((uint32_t)((wid * 16 + a_row_l) * 128 + ks * 32 + a_cb_l));
            uint32_t aH4[4], aL4[4];
            ldsm_x4(aH4[0], aH4[1], aH4[2], aH4[3], SQ_H + a_off);
            ldsm_x4(aL4[0], aL4[1], aL4[2], aL4[3], SQ_L + a_off);
#pragma unroll
            for (int np = 0; np < 8; np++) {
                uint32_t off = SMEM_SWIZZLE_128B(
                    (uint32_t)(((2 * np + (b_grp >> 1)) * 8 + b_row_l) * 128
                               + ks * 32 + (b_grp & 1) * 16));
                uint32_t bb[4];
                ldsm_x4(bb[0], bb[1], bb[2], bb[3], SK_H + off);
                mma_bf16(s[2 * np],     aH4, &bb[0]);
                mma_bf16(s[2 * np + 1], aH4, &bb[2]);
                mma_bf16(s[2 * np],     aL4, &bb[0]);
                mma_bf16(s[2 * np + 1], aL4, &bb[2]);
                ldsm_x4(bb[0], bb[1], bb[2], bb[3], SK_L + off);
                mma_bf16(s[2 * np],     aH4, &bb[0]);
                mma_bf16(s[2 * np + 1], aH4, &bb[2]);
            }
        }

        // ---- causal mask on diagonal tile ----
        if (kt == qi) {
            const int rl0 = wid * 16 + (lid >> 2);
#pragma unroll
            for (int nf = 0; nf < 16; nf++) {
                const int cl = nf * 8 + ((lid & 3) << 1);
#pragma unroll
                for (int c = 0; c < 4; c++) {
                    const int row = rl0 + ((c >> 1) << 3);
                    const int col = cl + (c & 1);
                    if (col > row) s[nf][c] = -1e30f;
                }
            }
        }

        // ---- online softmax (base-2, FMA-only exp) ----
        uint32_t ph[16][2];
#pragma unroll
        for (int rs = 0; rs < 2; rs++) {
            const int ci = rs << 1;
            float mt = -1e30f;
#pragma unroll
            for (int nf = 0; nf < 16; nf++)
                mt = fmaxf(mt, fmaxf(s[nf][ci], s[nf][ci + 1]));
            mt = fmaxf(mt, __shfl_xor_sync(0xffffffffu, mt, 1));
            mt = fmaxf(mt, __shfl_xor_sync(0xffffffffu, mt, 2));
            const float mn = fmaxf(m[rs], mt);
            const float alpha = exp2s(m[rs] - mn);
            m[rs] = mn;
            float rsum = 0.0f;
#pragma unroll
            for (int nf = 0; nf < 16; nf++) {
                float p0 = exp2s(s[nf][ci] - mn);
                float p1 = exp2s(s[nf][ci + 1] - mn);
                s[nf][ci] = p0;
                s[nf][ci + 1] = p1;
                rsum += p0 + p1;
            }
            rsum += __shfl_xor_sync(0xffffffffu, rsum, 1);
            rsum += __shfl_xor_sync(0xffffffffu, rsum, 2);
            l[rs] = l[rs] * alpha + rsum;
#pragma unroll
            for (int df = 0; df < 8; df++) {
                o[df][ci] *= alpha;
                o[df][ci + 1] *= alpha;
            }
        }
#pragma unroll
        for (int nf = 0; nf < 16; nf++) {
            __half2 p0 = __floats2half2_rn(s[nf][0], s[nf][1]);
            __half2 p1 = __floats2half2_rn(s[nf][2], s[nf][3]);
            ph[nf][0] = *(uint32_t*)&p0;
            ph[nf][1] = *(uint32_t*)&p1;
        }

        // ---- O += P V (fp16 mma, V via ldmatrix.trans) ----
#pragma unroll
        for (int j = 0; j < 8; j++) {
            uint32_t A4[4] = { ph[2 * j][0], ph[2 * j][1],
                               ph[2 * j + 1][0], ph[2 * j + 1][1] };
#pragma unroll
            for (int dp = 0; dp < 4; dp++) {
                uint32_t off = SMEM_SWIZZLE_128B(
                    (uint32_t)((j * 16 + (b_grp & 1) * 8 + b_row_l) * 128
                               + dp * 32 + (b_grp >> 1) * 16));
                uint32_t bb[4];
                ldsm_x4_t(bb[0], bb[1], bb[2], bb[3], SV + off);
                mma_f16(o[2 * dp],     A4, &bb[0]);
                mma_f16(o[2 * dp + 1], A4, &bb[2]);
            }
        }
    }

    // ---- epilogue: normalize, split bf16 hi/lo ----
    const float inv0 = 1.0f / l[0];
    const float inv1 = 1.0f / l[1];
    const int er = lid >> 2;
    const int ec = (lid & 3) << 1;
#pragma unroll
    for (int df = 0; df < 8; df++) {
        const int n = cbase + df * 8 + ec;
#pragma unroll
        for (int rs = 0; rs < 2; rs++) {
            const float inv = rs ? inv1 : inv0;
            const size_t row = rbase + q0 + wid * 16 + er + rs * 8;
            float v0 = o[df][2 * rs] * inv;
            float v1 = o[df][2 * rs + 1] * inv;
            __nv_bfloat16 h0 = __float2bfloat16(v0);
            __nv_bfloat16 h1 = __float2bfloat16(v1);
            *(__nv_bfloat162*)&Oh[row * 1024 + n] = __halves2bfloat162(h0, h1);
            *(__nv_bfloat162*)&Ol[row * 1024 + n] =
                __halves2bfloat162(__float2bfloat16(v0 - __bfloat162float(h0)),
                                   __float2bfloat16(v1 - __bfloat162float(h1)));
        }
    }
}

// ---------------------------------------------------------------------------
extern "C" void kernel_launch(void* const* d_in, const int* in_sizes, int n_in,
                              void* d_out, int out_size)
{
    (void)in_sizes; (void)n_in; (void)out_size;
    const float* x  = (const float*)d_in[0];
    const float* Wq = (const float*)d_in[1];
    const float* bq = (const float*)d_in[2];
    const float* Wk = (const float*)d_in[3];
    const float* bk = (const float*)d_in[4];
    const float* Wv = (const float*)d_in[5];
    const float* bv = (const float*)d_in[6];
    const float* Wo = (const float*)d_in[7];
    const float* bo = (const float*)d_in[8];
    float* out = (float*)d_out;

    __nv_bfloat16 *xh, *xl, *qh, *ql, *kh, *kl, *wth, *wtl;
    __half *v16;
    cudaGetSymbolAddress((void**)&xh, g_xh);
    cudaGetSymbolAddress((void**)&xl, g_xl);
    cudaGetSymbolAddress((void**)&qh, g_qh);
    cudaGetSymbolAddress((void**)&ql, g_ql);
    cudaGetSymbolAddress((void**)&kh, g_kh);
    cudaGetSymbolAddress((void**)&kl, g_kl);
    cudaGetSymbolAddress((void**)&v16, g_v16);
    cudaGetSymbolAddress((void**)&wth, g_wth);
    cudaGetSymbolAddress((void**)&wtl, g_wtl);

    const size_t WSZ = (size_t)D_MODEL * D_MODEL;
    const int GEMM_SMEM  = 66560;
    const int FLASH_SMEM = 132096;   // 32KB Q + 2 x 48KB stages + pad
    cudaFuncSetAttribute(gemm_qkv, cudaFuncAttributeMaxDynamicSharedMemorySize, GEMM_SMEM);
    cudaFuncSetAttribute(gemm_out, cudaFuncAttributeMaxDynamicSharedMemorySize, GEMM_SMEM);
    cudaFuncSetAttribute(flash_attn_tc, cudaFuncAttributeMaxDynamicSharedMemorySize, FLASH_SMEM);

    split_f32<<<(MROWS * D_MODEL / 4 + 255) / 256, 256>>>(x, xh, xl, MROWS * D_MODEL / 4);
    dim3 wt(32, 32);
    dim3 wtb(32, 8);
    wsplit_T<<<wt, wtb>>>(Wq, wth + 0 * WSZ, wtl + 0 * WSZ);
    wsplit_T<<<wt, wtb>>>(Wk, wth + 1 * WSZ, wtl + 1 * WSZ);
    wsplit_T<<<wt, wtb>>>(Wv, wth + 2 * WSZ, wtl + 2 * WSZ);
    wsplit_T<<<wt, wtb>>>(Wo, wth + 3 * WSZ, wtl + 3 * WSZ);

    dim3 gq(24, MROWS / 128);              // fused QKV: (24, 64)
    gemm_qkv<<<gq, 256, GEMM_SMEM>>>(xh, xl, wth, wtl, bq, bk, bv,
                                     qh, ql, kh, kl, v16);

    dim3 ga(SEQ / 128, NHEADS, BATCH);     // (16, 16, 4)
    flash_attn_tc<<<ga, 256, FLASH_SMEM>>>(qh, ql, kh, kl, v16, xh, xl);

    dim3 gg(D_MODEL / 128, MROWS / 128);   // (8, 64)
    gemm_out<<<gg, 256, GEMM_SMEM>>>(xh, xl, wth + 3 * WSZ, wtl + 3 * WSZ, bo, out);
}